// round 3
// baseline (speedup 1.0000x reference)
#include <cuda_runtime.h>
#include <cuda_bf16.h>
#include <cstdint>

// Problem constants
#define Bn   4
#define TTn  4096
#define Cn   1024
#define Hn   16
#define Kn   64
#define Tn   128
#define Nch  32
#define MTOK (Bn*TTn)          // 16384 tokens

// Scratch: 8 token-major buffers (64MB each) + chunk-entry states (33MB)
// idx: 0=xr (reused as yg), 1=xk, 2=xv, 3=xg, 4=r, 5=k, 6=v, 7=g
__device__ float g_buf[8][MTOK * Cn];
__device__ float g_states[(size_t)Nch * Bn * Hn * Kn * Kn];

// ---------------------------------------------------------------------------
// 1) time-shift + 4-way mix (vectorized float4, fully coalesced)
// ---------------------------------------------------------------------------
__global__ void __launch_bounds__(256) mix_kernel(
    const float* __restrict__ x,
    const float* __restrict__ mr, const float* __restrict__ mk,
    const float* __restrict__ mv, const float* __restrict__ mg)
{
    int idx = blockIdx.x * 256 + threadIdx.x;      // over MTOK*Cn/4 = 4194304
    const int C4 = Cn / 4;                          // 256
    int c4  = idx & (C4 - 1);
    int tok = idx >> 8;
    int t   = tok & (TTn - 1);

    float4 xc = ((const float4*)x)[idx];
    float4 xp = make_float4(0.f, 0.f, 0.f, 0.f);
    if (t > 0) xp = ((const float4*)x)[idx - C4];

    float4 f, o;
    // xr
    f = ((const float4*)mr)[c4];
    o.x = xc.x * f.x + xp.x * (1.f - f.x);
    o.y = xc.y * f.y + xp.y * (1.f - f.y);
    o.z = xc.z * f.z + xp.z * (1.f - f.z);
    o.w = xc.w * f.w + xp.w * (1.f - f.w);
    ((float4*)g_buf[0])[idx] = o;
    // xk
    f = ((const float4*)mk)[c4];
    o.x = xc.x * f.x + xp.x * (1.f - f.x);
    o.y = xc.y * f.y + xp.y * (1.f - f.y);
    o.z = xc.z * f.z + xp.z * (1.f - f.z);
    o.w = xc.w * f.w + xp.w * (1.f - f.w);
    ((float4*)g_buf[1])[idx] = o;
    // xv
    f = ((const float4*)mv)[c4];
    o.x = xc.x * f.x + xp.x * (1.f - f.x);
    o.y = xc.y * f.y + xp.y * (1.f - f.y);
    o.z = xc.z * f.z + xp.z * (1.f - f.z);
    o.w = xc.w * f.w + xp.w * (1.f - f.w);
    ((float4*)g_buf[2])[idx] = o;
    // xg
    f = ((const float4*)mg)[c4];
    o.x = xc.x * f.x + xp.x * (1.f - f.x);
    o.y = xc.y * f.y + xp.y * (1.f - f.y);
    o.z = xc.z * f.z + xp.z * (1.f - f.z);
    o.w = xc.w * f.w + xp.w * (1.f - f.w);
    ((float4*)g_buf[3])[idx] = o;
}

// ---------------------------------------------------------------------------
// 2) fp32 NT-SGEMM:  Y[M,N] = A[M,K] * W[N,K]^T   (M=16384, N=K=1024)
//    128x128 block tile, BK=16, 8x8 per-thread microtile, 256 threads.
//    act=1 applies SiLU in the epilogue (for the g projection).
// ---------------------------------------------------------------------------
__global__ void __launch_bounds__(256, 2) sgemm_nt(
    const float* __restrict__ A, const float* __restrict__ W,
    float* __restrict__ Y, int act)
{
    __shared__ float As[16][132];   // [k][m], padded
    __shared__ float Ws[16][132];   // [k][n], padded

    const int KK = Cn;
    int bm = blockIdx.y << 7;
    int bn = blockIdx.x << 7;
    int tid = threadIdx.x;
    int tr = tid >> 4, tc = tid & 15;

    float acc[8][8];
#pragma unroll
    for (int i = 0; i < 8; i++)
#pragma unroll
        for (int j = 0; j < 8; j++) acc[i][j] = 0.f;

    for (int k0 = 0; k0 < KK; k0 += 16) {
#pragma unroll
        for (int l = 0; l < 2; l++) {
            int t   = tid + (l << 8);      // 0..511
            int row = t >> 2;              // 0..127
            int kc  = (t & 3) << 2;        // 0,4,8,12
            float4 va = *(const float4*)(A + (size_t)(bm + row) * KK + k0 + kc);
            As[kc + 0][row] = va.x; As[kc + 1][row] = va.y;
            As[kc + 2][row] = va.z; As[kc + 3][row] = va.w;
            float4 vb = *(const float4*)(W + (size_t)(bn + row) * KK + k0 + kc);
            Ws[kc + 0][row] = vb.x; Ws[kc + 1][row] = vb.y;
            Ws[kc + 2][row] = vb.z; Ws[kc + 3][row] = vb.w;
        }
        __syncthreads();
#pragma unroll
        for (int k = 0; k < 16; k++) {
            float4 a0 = *(float4*)&As[k][(tr << 3) + 0];
            float4 a1 = *(float4*)&As[k][(tr << 3) + 4];
            float4 b0 = *(float4*)&Ws[k][(tc << 3) + 0];
            float4 b1 = *(float4*)&Ws[k][(tc << 3) + 4];
            float ar[8] = {a0.x, a0.y, a0.z, a0.w, a1.x, a1.y, a1.z, a1.w};
            float br[8] = {b0.x, b0.y, b0.z, b0.w, b1.x, b1.y, b1.z, b1.w};
#pragma unroll
            for (int i = 0; i < 8; i++)
#pragma unroll
                for (int j = 0; j < 8; j++)
                    acc[i][j] = fmaf(ar[i], br[j], acc[i][j]);
        }
        __syncthreads();
    }

#pragma unroll
    for (int i = 0; i < 8; i++) {
        size_t row = (size_t)(bm + (tr << 3) + i);
#pragma unroll
        for (int j = 0; j < 8; j += 4) {
            float v0 = acc[i][j], v1 = acc[i][j + 1], v2 = acc[i][j + 2], v3 = acc[i][j + 3];
            if (act) {
                v0 = v0 / (1.f + expf(-v0));
                v1 = v1 / (1.f + expf(-v1));
                v2 = v2 / (1.f + expf(-v2));
                v3 = v3 / (1.f + expf(-v3));
            }
            *(float4*)(Y + row * Cn + bn + (tc << 3) + j) = make_float4(v0, v1, v2, v3);
        }
    }
}

// ---------------------------------------------------------------------------
// 3) Pass A: sequential state scan per (b,h). Stores chunk-ENTRY state S_n.
//    S_{n+1} = ws*S_n + (k .* wk)^T @ v      (64x64 state in registers)
// ---------------------------------------------------------------------------
__global__ void __launch_bounds__(256, 1) states_kernel(const float* __restrict__ td)
{
    extern __shared__ float sm[];
    float* ks = sm;                 // [128][68] : k[j][kk] * wk[j]
    float* vs = sm + 128 * 68;      // [128][68]

    int b = blockIdx.x >> 4, h = blockIdx.x & 15;
    float et = expf(td[h]);         // decay = exp(-et); decay^p = exp(-et*p)
    float ws = expf(-et * 128.f);

    int tid = threadIdx.x;
    int tr = tid >> 4, tc = tid & 15;

    float S[4][4];
#pragma unroll
    for (int i = 0; i < 4; i++)
#pragma unroll
        for (int j = 0; j < 4; j++) S[i][j] = 0.f;

    const float* kg = &g_buf[5][(size_t)(b * TTn) * Cn + h * Kn];
    const float* vg = &g_buf[6][(size_t)(b * TTn) * Cn + h * Kn];

    for (int n = 0; n < Nch; n++) {
        // store chunk-entry state
        float* st = &g_states[(((size_t)n * Bn + b) * Hn + h) * (Kn * Kn)];
#pragma unroll
        for (int i = 0; i < 4; i++)
#pragma unroll
            for (int j = 0; j < 4; j++)
                st[(tr * 4 + i) * 64 + tc * 4 + j] = S[i][j];
        __syncthreads();   // prev compute done before reloading shared

        const float* kc_ = kg + (size_t)n * Tn * Cn;
        const float* vc_ = vg + (size_t)n * Tn * Cn;
#pragma unroll
        for (int l = 0; l < 8; l++) {
            int t4  = tid + (l << 8);    // 0..2047 float4s
            int row = t4 >> 4;
            int kc  = (t4 & 15) << 2;
            float4 kv = *(const float4*)(kc_ + (size_t)row * Cn + kc);
            float wkj = expf(-et * (float)(127 - row));
            ks[row * 68 + kc + 0] = kv.x * wkj;
            ks[row * 68 + kc + 1] = kv.y * wkj;
            ks[row * 68 + kc + 2] = kv.z * wkj;
            ks[row * 68 + kc + 3] = kv.w * wkj;
            float4 vv = *(const float4*)(vc_ + (size_t)row * Cn + kc);
            *(float4*)&vs[row * 68 + kc] = vv;
        }
        __syncthreads();

#pragma unroll
        for (int i = 0; i < 4; i++)
#pragma unroll
            for (int j = 0; j < 4; j++) S[i][j] *= ws;

        for (int j = 0; j < 128; j++) {
            float4 a  = *(float4*)&ks[j * 68 + (tr << 2)];
            float4 v4 = *(float4*)&vs[j * 68 + (tc << 2)];
            S[0][0] = fmaf(a.x, v4.x, S[0][0]); S[0][1] = fmaf(a.x, v4.y, S[0][1]);
            S[0][2] = fmaf(a.x, v4.z, S[0][2]); S[0][3] = fmaf(a.x, v4.w, S[0][3]);
            S[1][0] = fmaf(a.y, v4.x, S[1][0]); S[1][1] = fmaf(a.y, v4.y, S[1][1]);
            S[1][2] = fmaf(a.y, v4.z, S[1][2]); S[1][3] = fmaf(a.y, v4.w, S[1][3]);
            S[2][0] = fmaf(a.z, v4.x, S[2][0]); S[2][1] = fmaf(a.z, v4.y, S[2][1]);
            S[2][2] = fmaf(a.z, v4.z, S[2][2]); S[2][3] = fmaf(a.z, v4.w, S[2][3]);
            S[3][0] = fmaf(a.w, v4.x, S[3][0]); S[3][1] = fmaf(a.w, v4.y, S[3][1]);
            S[3][2] = fmaf(a.w, v4.z, S[3][2]); S[3][3] = fmaf(a.w, v4.w, S[3][3]);
        }
    }
}

// ---------------------------------------------------------------------------
// 4) Pass B: per (chunk,b,h) block — intra-chunk attention + state readback
//    + /8 + GroupNorm(head) + *g, writes yg (fully parallel, 2048 blocks)
// ---------------------------------------------------------------------------
#define PB_SMEM ((64*132*2 + 128*68 + 64*68 + 128*132 + 3*128) * 4)

__global__ void __launch_bounds__(256, 1) passB_kernel(
    const float* __restrict__ td, const float* __restrict__ tf,
    const float* __restrict__ lnw, const float* __restrict__ lnb)
{
    extern __shared__ float sm[];
    float* rT   = sm;                    // [64][132]  r^T  (k-major)
    float* kT   = rT + 64 * 132;         // [64][132]  k^T
    float* vsm  = kT + 64 * 132;         // [128][68]  v row-major
    float* Ssm  = vsm + 128 * 68;        // [64][68]   chunk-entry state
    float* att  = Ssm + 64 * 68;         // [128][132]; later reused as out[128][68]
    float* dp   = att + 128 * 132;       // [128] decay powers
    float* mu_s = dp + 128;              // [128]
    float* rs_s = mu_s + 128;            // [128]

    int bidx = blockIdx.x;
    int n = bidx >> 6, bh = bidx & 63, b = bh >> 4, h = bh & 15;
    int tid = threadIdx.x;
    int tr = tid >> 4, tc = tid & 15;

    float et = expf(td[h]);
    float u  = tf[h];
    if (tid < 128) dp[tid] = expf(-et * (float)tid);

    const size_t base = ((size_t)(b * TTn + n * Tn)) * Cn + h * Kn;
    const float* rg = &g_buf[4][base];
    const float* kg = &g_buf[5][base];
    const float* vg = &g_buf[6][base];

#pragma unroll
    for (int l = 0; l < 8; l++) {
        int t4  = tid + (l << 8);
        int row = t4 >> 4;
        int kc  = (t4 & 15) << 2;
        float4 rv = *(const float4*)(rg + (size_t)row * Cn + kc);
        rT[(kc + 0) * 132 + row] = rv.x; rT[(kc + 1) * 132 + row] = rv.y;
        rT[(kc + 2) * 132 + row] = rv.z; rT[(kc + 3) * 132 + row] = rv.w;
        float4 kv = *(const float4*)(kg + (size_t)row * Cn + kc);
        kT[(kc + 0) * 132 + row] = kv.x; kT[(kc + 1) * 132 + row] = kv.y;
        kT[(kc + 2) * 132 + row] = kv.z; kT[(kc + 3) * 132 + row] = kv.w;
        float4 vv = *(const float4*)(vg + (size_t)row * Cn + kc);
        *(float4*)&vsm[row * 68 + kc] = vv;
    }
    const float* Sg = &g_states[(((size_t)n * Bn + b) * Hn + h) * (Kn * Kn)];
#pragma unroll
    for (int l = 0; l < 4; l++) {
        int t4  = tid + (l << 8);   // 0..1023 float4s
        int row = t4 >> 4;
        int kc  = (t4 & 15) << 2;
        *(float4*)&Ssm[row * 68 + kc] = *(const float4*)(Sg + row * 64 + kc);
    }
    __syncthreads();

    // ---- stage 1: att = (r @ k^T) .* w_mat ----
    {
        float acc[8][8];
#pragma unroll
        for (int i = 0; i < 8; i++)
#pragma unroll
            for (int j = 0; j < 8; j++) acc[i][j] = 0.f;

        for (int kk = 0; kk < 64; kk++) {
            float4 a0 = *(float4*)&rT[kk * 132 + (tr << 3) + 0];
            float4 a1 = *(float4*)&rT[kk * 132 + (tr << 3) + 4];
            float4 b0 = *(float4*)&kT[kk * 132 + (tc << 3) + 0];
            float4 b1 = *(float4*)&kT[kk * 132 + (tc << 3) + 4];
            float ar[8] = {a0.x, a0.y, a0.z, a0.w, a1.x, a1.y, a1.z, a1.w};
            float br[8] = {b0.x, b0.y, b0.z, b0.w, b1.x, b1.y, b1.z, b1.w};
#pragma unroll
            for (int i = 0; i < 8; i++)
#pragma unroll
                for (int j = 0; j < 8; j++)
                    acc[i][j] = fmaf(ar[i], br[j], acc[i][j]);
        }
#pragma unroll
        for (int i = 0; i < 8; i++) {
            int row = (tr << 3) + i;
#pragma unroll
            for (int j = 0; j < 8; j++) {
                int col = (tc << 3) + j;
                float w = (row > col) ? dp[row - col - 1] : ((row == col) ? u : 0.f);
                att[row * 132 + col] = acc[i][j] * w;
            }
        }
    }
    __syncthreads();

    // ---- stage 2: out = att@v + diag(wb) * (r@S) ----
    float a2[8][4], aS[8][4];
#pragma unroll
    for (int i = 0; i < 8; i++)
#pragma unroll
        for (int j = 0; j < 4; j++) { a2[i][j] = 0.f; aS[i][j] = 0.f; }

    for (int j = 0; j < 128; j++) {
        float4 bv = *(float4*)&vsm[j * 68 + (tc << 2)];
#pragma unroll
        for (int i = 0; i < 8; i++) {
            float a = att[((tr << 3) + i) * 132 + j];
            a2[i][0] = fmaf(a, bv.x, a2[i][0]);
            a2[i][1] = fmaf(a, bv.y, a2[i][1]);
            a2[i][2] = fmaf(a, bv.z, a2[i][2]);
            a2[i][3] = fmaf(a, bv.w, a2[i][3]);
        }
    }
    for (int kk = 0; kk < 64; kk++) {
        float4 a0 = *(float4*)&rT[kk * 132 + (tr << 3) + 0];
        float4 a1 = *(float4*)&rT[kk * 132 + (tr << 3) + 4];
        float4 bs = *(float4*)&Ssm[kk * 68 + (tc << 2)];
        float ar[8] = {a0.x, a0.y, a0.z, a0.w, a1.x, a1.y, a1.z, a1.w};
#pragma unroll
        for (int i = 0; i < 8; i++) {
            aS[i][0] = fmaf(ar[i], bs.x, aS[i][0]);
            aS[i][1] = fmaf(ar[i], bs.y, aS[i][1]);
            aS[i][2] = fmaf(ar[i], bs.z, aS[i][2]);
            aS[i][3] = fmaf(ar[i], bs.w, aS[i][3]);
        }
    }
    __syncthreads();   // everyone done reading att before reuse as out staging

#pragma unroll
    for (int i = 0; i < 8; i++) {
        int row = (tr << 3) + i;
        float wb = dp[row];
        float4 o;
        o.x = a2[i][0] + wb * aS[i][0];
        o.y = a2[i][1] + wb * aS[i][1];
        o.z = a2[i][2] + wb * aS[i][2];
        o.w = a2[i][3] + wb * aS[i][3];
        *(float4*)&att[row * 68 + (tc << 2)] = o;  // out staging
    }
    __syncthreads();

    // ---- GroupNorm stats per row (over 64 head channels of y = out/8) ----
    if (tid < 128) {
        float s1 = 0.f, s2 = 0.f;
        const float* orow = &att[tid * 68];
#pragma unroll
        for (int c = 0; c < 64; c++) {
            float v = orow[c] * 0.125f;
            s1 += v; s2 += v * v;
        }
        float mu  = s1 * (1.f / 64.f);
        float var = s2 * (1.f / 64.f) - mu * mu;
        mu_s[tid] = mu;
        rs_s[tid] = rsqrtf(var + 1e-5f);
    }
    __syncthreads();

    // ---- normalize, scale/shift, multiply by g, write yg (coalesced) ----
    const float* gg = &g_buf[7][base];
    float* yg = &g_buf[0][base];
#pragma unroll
    for (int l = 0; l < 8; l++) {
        int t4  = tid + (l << 8);
        int row = t4 >> 4;
        int kc  = (t4 & 15) << 2;
        float mu = mu_s[row], rs = rs_s[row];
        float4 o  = *(float4*)&att[row * 68 + kc];
        float4 w4 = *(const float4*)(lnw + h * 64 + kc);
        float4 b4 = *(const float4*)(lnb + h * 64 + kc);
        float4 g4 = *(const float4*)(gg + (size_t)row * Cn + kc);
        float4 y;
        y.x = ((o.x * 0.125f - mu) * rs * w4.x + b4.x) * g4.x;
        y.y = ((o.y * 0.125f - mu) * rs * w4.y + b4.y) * g4.y;
        y.z = ((o.z * 0.125f - mu) * rs * w4.z + b4.z) * g4.z;
        y.w = ((o.w * 0.125f - mu) * rs * w4.w + b4.w) * g4.w;
        *(float4*)(yg + (size_t)row * Cn + kc) = y;
    }
}

// ---------------------------------------------------------------------------
extern "C" void kernel_launch(void* const* d_in, const int* in_sizes, int n_in,
                              void* d_out, int out_size)
{
    (void)in_sizes; (void)n_in; (void)out_size;
    const float* xq  = (const float*)d_in[0];
    const float* tmk = (const float*)d_in[1];
    const float* tmv = (const float*)d_in[2];
    const float* tmr = (const float*)d_in[3];
    const float* tmg = (const float*)d_in[4];
    const float* td  = (const float*)d_in[5];
    const float* tf  = (const float*)d_in[6];
    const float* Wr  = (const float*)d_in[7];
    const float* Wk  = (const float*)d_in[8];
    const float* Wv  = (const float*)d_in[9];
    const float* Wg  = (const float*)d_in[10];
    const float* Wo  = (const float*)d_in[11];
    const float* lnw = (const float*)d_in[12];
    const float* lnb = (const float*)d_in[13];
    float* out = (float*)d_out;

    float* buf = nullptr;
    cudaGetSymbolAddress((void**)&buf, g_buf);
    float* b0 = buf + (size_t)0 * MTOK * Cn;   // xr / yg
    float* b1 = buf + (size_t)1 * MTOK * Cn;   // xk
    float* b2 = buf + (size_t)2 * MTOK * Cn;   // xv
    float* b3 = buf + (size_t)3 * MTOK * Cn;   // xg
    float* br = buf + (size_t)4 * MTOK * Cn;   // r
    float* bk = buf + (size_t)5 * MTOK * Cn;   // k
    float* bv = buf + (size_t)6 * MTOK * Cn;   // v
    float* bg = buf + (size_t)7 * MTOK * Cn;   // g

    mix_kernel<<<(MTOK * Cn / 4) / 256, 256>>>(xq, tmr, tmk, tmv, tmg);

    dim3 gdim(Cn / 128, MTOK / 128);   // (8, 128)
    sgemm_nt<<<gdim, 256>>>(b0, Wr, br, 0);
    sgemm_nt<<<gdim, 256>>>(b1, Wk, bk, 0);
    sgemm_nt<<<gdim, 256>>>(b2, Wv, bv, 0);
    sgemm_nt<<<gdim, 256>>>(b3, Wg, bg, 1);   // SiLU

    int smA = 2 * 128 * 68 * 4;
    cudaFuncSetAttribute(states_kernel, cudaFuncAttributeMaxDynamicSharedMemorySize, smA);
    states_kernel<<<Bn * Hn, 256, smA>>>(td);

    cudaFuncSetAttribute(passB_kernel, cudaFuncAttributeMaxDynamicSharedMemorySize, PB_SMEM);
    passB_kernel<<<Nch * Bn * Hn, 256, PB_SMEM>>>(td, tf, lnw, lnb);

    sgemm_nt<<<gdim, 256>>>(b0, Wo, out, 0);
}

// round 7
// speedup vs baseline: 1.9102x; 1.9102x over previous
#include <cuda_runtime.h>
#include <cuda_fp16.h>
#include <cstdint>

// Problem constants
#define Bn   4
#define TTn  4096
#define Cn   1024
#define Hn   16
#define Kn   64
#define Tn   128
#define Nch  32
#define MTOK (Bn*TTn)          // 16384 tokens

// Scratch:
//  g_h16: fp16 hi/lo pairs: 0/1=xr 2/3=xk 4/5=xv 6/7=xg 8/9=yg   (10 x 32MB)
//  g_f32: 0=r 1=k 2=v 3=g (fp32 for attention)                    (4 x 64MB)
//  g_w16: weight hi/lo: 0/1=Wr 2/3=Wk 4/5=Wv 6/7=Wg 8/9=Wo        (10 x 2MB)
__device__ __half g_h16[10][(size_t)MTOK * Cn];
__device__ float  g_f32[4][(size_t)MTOK * Cn];
__device__ __half g_w16[10][(size_t)Cn * Cn];
__device__ float  g_states[(size_t)Nch * Bn * Hn * Kn * Kn];

// ---------------------------------------------------------------------------
// helpers (baseline PTX only: cp.async sm_80, ldmatrix sm_75, mma.sync sm_80)
// ---------------------------------------------------------------------------
__device__ __forceinline__ uint32_t s2u(const void* p) {
    return (uint32_t)__cvta_generic_to_shared(p);
}
#define CP16(dst, src) asm volatile("cp.async.cg.shared.global [%0], [%1], 16;" :: "r"(dst), "l"(src) : "memory")
#define CP_COMMIT()    asm volatile("cp.async.commit_group;" ::: "memory")
#define CP_WAIT1()     asm volatile("cp.async.wait_group 1;" ::: "memory")
#define CP_WAIT0()     asm volatile("cp.async.wait_group 0;" ::: "memory")

#define LDSM4(r, a) asm volatile( \
    "ldmatrix.sync.aligned.m8n8.x4.shared.b16 {%0,%1,%2,%3}, [%4];" \
    : "=r"((r)[0]), "=r"((r)[1]), "=r"((r)[2]), "=r"((r)[3]) : "r"(a))

#define MMA16816(c, a, b) asm volatile( \
    "mma.sync.aligned.m16n8k16.row.col.f32.f16.f16.f32 " \
    "{%0,%1,%2,%3}, {%4,%5,%6,%7}, {%8,%9}, {%0,%1,%2,%3};" \
    : "+f"((c)[0]), "+f"((c)[1]), "+f"((c)[2]), "+f"((c)[3]) \
    : "r"((a)[0]), "r"((a)[1]), "r"((a)[2]), "r"((a)[3]), \
      "r"((b)[0]), "r"((b)[1]))

__device__ __forceinline__ uint32_t swz(uint32_t o) { return o ^ ((o >> 3) & 0x70); }

// fp32 -> fp16 hi/lo split, 4 elements, packed stores
__device__ __forceinline__ void split_store4(__half* hb, __half* lb, size_t idx4, float4 o) {
    __half h0 = __float2half_rn(o.x), h1 = __float2half_rn(o.y);
    __half h2 = __float2half_rn(o.z), h3 = __float2half_rn(o.w);
    __half l0 = __float2half_rn(o.x - __half2float(h0));
    __half l1 = __float2half_rn(o.y - __half2float(h1));
    __half l2 = __float2half_rn(o.z - __half2float(h2));
    __half l3 = __float2half_rn(o.w - __half2float(h3));
    uint2 hv, lv;
    hv.x = (uint32_t)__half_as_ushort(h0) | ((uint32_t)__half_as_ushort(h1) << 16);
    hv.y = (uint32_t)__half_as_ushort(h2) | ((uint32_t)__half_as_ushort(h3) << 16);
    lv.x = (uint32_t)__half_as_ushort(l0) | ((uint32_t)__half_as_ushort(l1) << 16);
    lv.y = (uint32_t)__half_as_ushort(l2) | ((uint32_t)__half_as_ushort(l3) << 16);
    ((uint2*)hb)[idx4] = hv;
    ((uint2*)lb)[idx4] = lv;
}

// ---------------------------------------------------------------------------
// 1) time-shift + 4-way mix -> fp16 hi/lo outputs
// ---------------------------------------------------------------------------
__global__ void __launch_bounds__(256) mix_split(
    const float* __restrict__ x,
    const float* __restrict__ mr, const float* __restrict__ mk,
    const float* __restrict__ mv, const float* __restrict__ mg)
{
    int idx = blockIdx.x * 256 + threadIdx.x;   // over MTOK*Cn/4
    const int C4 = Cn / 4;
    int c4  = idx & (C4 - 1);
    int tok = idx >> 8;
    int t   = tok & (TTn - 1);

    float4 xc = ((const float4*)x)[idx];
    float4 xp = make_float4(0.f, 0.f, 0.f, 0.f);
    if (t > 0) xp = ((const float4*)x)[idx - C4];

    const float* mixes[4] = {mr, mk, mv, mg};
#pragma unroll
    for (int m = 0; m < 4; m++) {
        float4 f = ((const float4*)mixes[m])[c4];
        float4 o;
        o.x = xc.x * f.x + xp.x * (1.f - f.x);
        o.y = xc.y * f.y + xp.y * (1.f - f.y);
        o.z = xc.z * f.z + xp.z * (1.f - f.z);
        o.w = xc.w * f.w + xp.w * (1.f - f.w);
        split_store4(g_h16[2 * m], g_h16[2 * m + 1], (size_t)idx, o);
    }
}

// ---------------------------------------------------------------------------
// 1b) weight fp32 -> fp16 hi/lo
// ---------------------------------------------------------------------------
__global__ void __launch_bounds__(256) wsplit(
    const float* __restrict__ W, __half* __restrict__ hi, __half* __restrict__ lo)
{
    int idx = blockIdx.x * 256 + threadIdx.x;   // over Cn*Cn/4
    float4 w = ((const float4*)W)[idx];
    split_store4(hi, lo, (size_t)idx, w);
}

// ---------------------------------------------------------------------------
// 2) HMMA fp16-split GEMM:  Y[M,N] = A[M,K] * W[N,K]^T  (fp32-accurate)
//    BM=BN=128, BK=32, 3-stage cp.async pipeline, mma.sync.m16n8k16
//    8 warps: warp_m = wid&1 (64 rows), warp_n = wid>>1 (32 cols)
// ---------------------------------------------------------------------------
#define BM 128
#define BN 128
#define BK 32
#define NCHUNK (Cn / BK)        // 32
#define TILE_B (BM * BK * 2)    // 8192 bytes per half-tile
#define STG_BYTES (4 * TILE_B)  // 32768 (Ahi, Alo, Bhi, Blo)
#define GEMM_SMEM (3 * STG_BYTES)

__global__ void __launch_bounds__(256, 1)
gemm16(const __half* __restrict__ Ahi, const __half* __restrict__ Alo,
       const __half* __restrict__ Bhi, const __half* __restrict__ Blo,
       float* __restrict__ Y, int act)
{
    extern __shared__ char smem[];
    uint32_t sb = s2u(smem);
    int tid = threadIdx.x, wid = tid >> 5, lane = tid & 31;
    int bm = blockIdx.y << 7;
    int bn = blockIdx.x << 7;
    int wm = (wid & 1) << 6;    // 0 / 64
    int wn = (wid >> 1) << 5;   // 0 / 32 / 64 / 96

    auto load_stage = [&](int s, int c) {
        uint32_t so = sb + (uint32_t)s * STG_BYTES;
#pragma unroll
        for (int i = 0; i < 2; i++) {
            int idx = tid + (i << 8);          // 0..511
            int row = idx >> 2;                // 0..127
            uint32_t cb = (idx & 3) << 4;      // 0,16,32,48 bytes
            uint32_t d = swz(row * 64 + cb);
            size_t go = ((size_t)(bm + row) << 11) + (size_t)c * 64 + cb;
            CP16(so + d,         (const char*)Ahi + go);
            CP16(so + 8192 + d,  (const char*)Alo + go);
            size_t gb = ((size_t)(bn + row) << 11) + (size_t)c * 64 + cb;
            CP16(so + 16384 + d, (const char*)Bhi + gb);
            CP16(so + 24576 + d, (const char*)Blo + gb);
        }
        CP_COMMIT();
    };

    float acc[4][4][4];
#pragma unroll
    for (int mt = 0; mt < 4; mt++)
#pragma unroll
        for (int nt = 0; nt < 4; nt++)
#pragma unroll
            for (int q = 0; q < 4; q++) acc[mt][nt][q] = 0.f;

    load_stage(0, 0);
    load_stage(1, 1);

    for (int c = 0; c < NCHUNK; c++) {
        int s = c % 3;
        if (c + 2 < NCHUNK) CP_WAIT1(); else CP_WAIT0();
        __syncthreads();
        if (c + 2 < NCHUNK) load_stage((c + 2) % 3, c + 2);

        uint32_t so = sb + (uint32_t)s * STG_BYTES;
#pragma unroll
        for (int s16 = 0; s16 < 2; s16++) {
            uint32_t ah[4][4], al[4][4], bh[4][2], bl[4][2];
#pragma unroll
            for (int mt = 0; mt < 4; mt++) {
                int row = wm + mt * 16 + (lane & 15);
                uint32_t o = swz(row * 64 + s16 * 32 + ((lane >> 4) << 4));
                LDSM4(ah[mt], so + o);
                LDSM4(al[mt], so + 8192 + o);
            }
#pragma unroll
            for (int bt = 0; bt < 2; bt++) {
                int row = wn + bt * 16 + (lane & 15);
                uint32_t o = swz(row * 64 + s16 * 32 + ((lane >> 4) << 4));
                uint32_t r[4];
                LDSM4(r, so + 16384 + o);
                bh[2 * bt][0] = r[0]; bh[2 * bt][1] = r[2];
                bh[2 * bt + 1][0] = r[1]; bh[2 * bt + 1][1] = r[3];
                LDSM4(r, so + 24576 + o);
                bl[2 * bt][0] = r[0]; bl[2 * bt][1] = r[2];
                bl[2 * bt + 1][0] = r[1]; bl[2 * bt + 1][1] = r[3];
            }
#pragma unroll
            for (int mt = 0; mt < 4; mt++)
#pragma unroll
                for (int nt = 0; nt < 4; nt++) {
                    MMA16816(acc[mt][nt], ah[mt], bh[nt]);
                    MMA16816(acc[mt][nt], al[mt], bh[nt]);
                    MMA16816(acc[mt][nt], ah[mt], bl[nt]);
                }
        }
    }

    // epilogue
#pragma unroll
    for (int mt = 0; mt < 4; mt++) {
        int r0 = bm + wm + mt * 16 + (lane >> 2);
#pragma unroll
        for (int nt = 0; nt < 4; nt++) {
            int col = bn + wn + nt * 8 + ((lane & 3) << 1);
            float v0 = acc[mt][nt][0], v1 = acc[mt][nt][1];
            float v2 = acc[mt][nt][2], v3 = acc[mt][nt][3];
            if (act) {
                v0 = v0 / (1.f + expf(-v0));
                v1 = v1 / (1.f + expf(-v1));
                v2 = v2 / (1.f + expf(-v2));
                v3 = v3 / (1.f + expf(-v3));
            }
            *(float2*)(Y + (size_t)r0 * Cn + col)       = make_float2(v0, v1);
            *(float2*)(Y + (size_t)(r0 + 8) * Cn + col) = make_float2(v2, v3);
        }
    }
}

// ---------------------------------------------------------------------------
// 3) Pass A: sequential state scan per (b,h). Stores chunk-ENTRY state S_n.
// ---------------------------------------------------------------------------
__global__ void __launch_bounds__(256, 1) states_kernel(const float* __restrict__ td)
{
    extern __shared__ float sm[];
    float* ks = sm;                 // [128][68] : k[j][kk] * wk[j]
    float* vs = sm + 128 * 68;      // [128][68]

    int b = blockIdx.x >> 4, h = blockIdx.x & 15;
    float et = expf(td[h]);
    float ws = expf(-et * 128.f);

    int tid = threadIdx.x;
    int tr = tid >> 4, tc = tid & 15;

    float S[4][4];
#pragma unroll
    for (int i = 0; i < 4; i++)
#pragma unroll
        for (int j = 0; j < 4; j++) S[i][j] = 0.f;

    const float* kg = &g_f32[1][(size_t)(b * TTn) * Cn + h * Kn];
    const float* vg = &g_f32[2][(size_t)(b * TTn) * Cn + h * Kn];

    for (int n = 0; n < Nch; n++) {
        float* st = &g_states[(((size_t)n * Bn + b) * Hn + h) * (Kn * Kn)];
#pragma unroll
        for (int i = 0; i < 4; i++)
#pragma unroll
            for (int j = 0; j < 4; j++)
                st[(tr * 4 + i) * 64 + tc * 4 + j] = S[i][j];
        __syncthreads();

        const float* kc_ = kg + (size_t)n * Tn * Cn;
        const float* vc_ = vg + (size_t)n * Tn * Cn;
#pragma unroll
        for (int l = 0; l < 8; l++) {
            int t4  = tid + (l << 8);
            int row = t4 >> 4;
            int kc  = (t4 & 15) << 2;
            float4 kv = *(const float4*)(kc_ + (size_t)row * Cn + kc);
            float wkj = expf(-et * (float)(127 - row));
            ks[row * 68 + kc + 0] = kv.x * wkj;
            ks[row * 68 + kc + 1] = kv.y * wkj;
            ks[row * 68 + kc + 2] = kv.z * wkj;
            ks[row * 68 + kc + 3] = kv.w * wkj;
            float4 vv = *(const float4*)(vc_ + (size_t)row * Cn + kc);
            *(float4*)&vs[row * 68 + kc] = vv;
        }
        __syncthreads();

#pragma unroll
        for (int i = 0; i < 4; i++)
#pragma unroll
            for (int j = 0; j < 4; j++) S[i][j] *= ws;

        for (int j = 0; j < 128; j++) {
            float4 a  = *(float4*)&ks[j * 68 + (tr << 2)];
            float4 v4 = *(float4*)&vs[j * 68 + (tc << 2)];
            S[0][0] = fmaf(a.x, v4.x, S[0][0]); S[0][1] = fmaf(a.x, v4.y, S[0][1]);
            S[0][2] = fmaf(a.x, v4.z, S[0][2]); S[0][3] = fmaf(a.x, v4.w, S[0][3]);
            S[1][0] = fmaf(a.y, v4.x, S[1][0]); S[1][1] = fmaf(a.y, v4.y, S[1][1]);
            S[1][2] = fmaf(a.y, v4.z, S[1][2]); S[1][3] = fmaf(a.y, v4.w, S[1][3]);
            S[2][0] = fmaf(a.z, v4.x, S[2][0]); S[2][1] = fmaf(a.z, v4.y, S[2][1]);
            S[2][2] = fmaf(a.z, v4.z, S[2][2]); S[2][3] = fmaf(a.z, v4.w, S[2][3]);
            S[3][0] = fmaf(a.w, v4.x, S[3][0]); S[3][1] = fmaf(a.w, v4.y, S[3][1]);
            S[3][2] = fmaf(a.w, v4.z, S[3][2]); S[3][3] = fmaf(a.w, v4.w, S[3][3]);
        }
    }
}

// ---------------------------------------------------------------------------
// 4) Pass B: intra-chunk attention + state + GroupNorm + *g -> yg (fp16 hi/lo)
// ---------------------------------------------------------------------------
#define PB_SMEM ((64*132*2 + 128*68 + 64*68 + 128*132 + 3*128) * 4)

__global__ void __launch_bounds__(256, 1) passB_kernel(
    const float* __restrict__ td, const float* __restrict__ tf,
    const float* __restrict__ lnw, const float* __restrict__ lnb)
{
    extern __shared__ float sm[];
    float* rT   = sm;                    // [64][132]
    float* kT   = rT + 64 * 132;         // [64][132]
    float* vsm  = kT + 64 * 132;         // [128][68]
    float* Ssm  = vsm + 128 * 68;        // [64][68]
    float* att  = Ssm + 64 * 68;         // [128][132]; reused as out[128][68]
    float* dp   = att + 128 * 132;       // [128]
    float* mu_s = dp + 128;
    float* rs_s = mu_s + 128;

    int bidx = blockIdx.x;
    int n = bidx >> 6, bh = bidx & 63, b = bh >> 4, h = bh & 15;
    int tid = threadIdx.x;
    int tr = tid >> 4, tc = tid & 15;

    float et = expf(td[h]);
    float u  = tf[h];
    if (tid < 128) dp[tid] = expf(-et * (float)tid);

    const size_t base = ((size_t)(b * TTn + n * Tn)) * Cn + h * Kn;
    const float* rg = &g_f32[0][base];
    const float* kg = &g_f32[1][base];
    const float* vg = &g_f32[2][base];

#pragma unroll
    for (int l = 0; l < 8; l++) {
        int t4  = tid + (l << 8);
        int row = t4 >> 4;
        int kc  = (t4 & 15) << 2;
        float4 rv = *(const float4*)(rg + (size_t)row * Cn + kc);
        rT[(kc + 0) * 132 + row] = rv.x; rT[(kc + 1) * 132 + row] = rv.y;
        rT[(kc + 2) * 132 + row] = rv.z; rT[(kc + 3) * 132 + row] = rv.w;
        float4 kv = *(const float4*)(kg + (size_t)row * Cn + kc);
        kT[(kc + 0) * 132 + row] = kv.x; kT[(kc + 1) * 132 + row] = kv.y;
        kT[(kc + 2) * 132 + row] = kv.z; kT[(kc + 3) * 132 + row] = kv.w;
        float4 vv = *(const float4*)(vg + (size_t)row * Cn + kc);
        *(float4*)&vsm[row * 68 + kc] = vv;
    }
    const float* Sg = &g_states[(((size_t)n * Bn + b) * Hn + h) * (Kn * Kn)];
#pragma unroll
    for (int l = 0; l < 4; l++) {
        int t4  = tid + (l << 8);
        int row = t4 >> 4;
        int kc  = (t4 & 15) << 2;
        *(float4*)&Ssm[row * 68 + kc] = *(const float4*)(Sg + row * 64 + kc);
    }
    __syncthreads();

    // ---- stage 1: att = (r @ k^T) .* w_mat ----
    {
        float acc[8][8];
#pragma unroll
        for (int i = 0; i < 8; i++)
#pragma unroll
            for (int j = 0; j < 8; j++) acc[i][j] = 0.f;

        for (int kk = 0; kk < 64; kk++) {
            float4 a0 = *(float4*)&rT[kk * 132 + (tr << 3) + 0];
            float4 a1 = *(float4*)&rT[kk * 132 + (tr << 3) + 4];
            float4 b0 = *(float4*)&kT[kk * 132 + (tc << 3) + 0];
            float4 b1 = *(float4*)&kT[kk * 132 + (tc << 3) + 4];
            float ar[8] = {a0.x, a0.y, a0.z, a0.w, a1.x, a1.y, a1.z, a1.w};
            float br[8] = {b0.x, b0.y, b0.z, b0.w, b1.x, b1.y, b1.z, b1.w};
#pragma unroll
            for (int i = 0; i < 8; i++)
#pragma unroll
                for (int j = 0; j < 8; j++)
                    acc[i][j] = fmaf(ar[i], br[j], acc[i][j]);
        }
#pragma unroll
        for (int i = 0; i < 8; i++) {
            int row = (tr << 3) + i;
#pragma unroll
            for (int j = 0; j < 8; j++) {
                int col = (tc << 3) + j;
                float w = (row > col) ? dp[row - col - 1] : ((row == col) ? u : 0.f);
                att[row * 132 + col] = acc[i][j] * w;
            }
        }
    }
    __syncthreads();

    // ---- stage 2: out = att@v + diag(wb) * (r@S) ----
    float a2[8][4], aS[8][4];
#pragma unroll
    for (int i = 0; i < 8; i++)
#pragma unroll
        for (int j = 0; j < 4; j++) { a2[i][j] = 0.f; aS[i][j] = 0.f; }

    for (int j = 0; j < 128; j++) {
        float4 bv = *(float4*)&vsm[j * 68 + (tc << 2)];
#pragma unroll
        for (int i = 0; i < 8; i++) {
            float a = att[((tr << 3) + i) * 132 + j];
            a2[i][0] = fmaf(a, bv.x, a2[i][0]);
            a2[i][1] = fmaf(a, bv.y, a2[i][1]);
            a2[i][2] = fmaf(a, bv.z, a2[i][2]);
            a2[i][3] = fmaf(a, bv.w, a2[i][3]);
        }
    }
    for (int kk = 0; kk < 64; kk++) {
        float4 a0 = *(float4*)&rT[kk * 132 + (tr << 3) + 0];
        float4 a1 = *(float4*)&rT[kk * 132 + (tr << 3) + 4];
        float4 bs = *(float4*)&Ssm[kk * 68 + (tc << 2)];
        float ar[8] = {a0.x, a0.y, a0.z, a0.w, a1.x, a1.y, a1.z, a1.w};
#pragma unroll
        for (int i = 0; i < 8; i++) {
            aS[i][0] = fmaf(ar[i], bs.x, aS[i][0]);
            aS[i][1] = fmaf(ar[i], bs.y, aS[i][1]);
            aS[i][2] = fmaf(ar[i], bs.z, aS[i][2]);
            aS[i][3] = fmaf(ar[i], bs.w, aS[i][3]);
        }
    }
    __syncthreads();

#pragma unroll
    for (int i = 0; i < 8; i++) {
        int row = (tr << 3) + i;
        float wb = dp[row];
        float4 o;
        o.x = a2[i][0] + wb * aS[i][0];
        o.y = a2[i][1] + wb * aS[i][1];
        o.z = a2[i][2] + wb * aS[i][2];
        o.w = a2[i][3] + wb * aS[i][3];
        *(float4*)&att[row * 68 + (tc << 2)] = o;
    }
    __syncthreads();

    if (tid < 128) {
        float s1 = 0.f, s2 = 0.f;
        const float* orow = &att[tid * 68];
#pragma unroll
        for (int c = 0; c < 64; c++) {
            float v = orow[c] * 0.125f;
            s1 += v; s2 += v * v;
        }
        float mu  = s1 * (1.f / 64.f);
        float var = s2 * (1.f / 64.f) - mu * mu;
        mu_s[tid] = mu;
        rs_s[tid] = rsqrtf(var + 1e-5f);
    }
    __syncthreads();

    const float* gg = &g_f32[3][base];
#pragma unroll
    for (int l = 0; l < 8; l++) {
        int t4  = tid + (l << 8);
        int row = t4 >> 4;
        int kc  = (t4 & 15) << 2;
        float mu = mu_s[row], rs = rs_s[row];
        float4 o  = *(float4*)&att[row * 68 + kc];
        float4 w4 = *(const float4*)(lnw + h * 64 + kc);
        float4 b4 = *(const float4*)(lnb + h * 64 + kc);
        float4 g4 = *(const float4*)(gg + (size_t)row * Cn + kc);
        float4 y;
        y.x = ((o.x * 0.125f - mu) * rs * w4.x + b4.x) * g4.x;
        y.y = ((o.y * 0.125f - mu) * rs * w4.y + b4.y) * g4.y;
        y.z = ((o.z * 0.125f - mu) * rs * w4.z + b4.z) * g4.z;
        y.w = ((o.w * 0.125f - mu) * rs * w4.w + b4.w) * g4.w;
        size_t e = base + (size_t)row * Cn + kc;
        split_store4(g_h16[8], g_h16[9], e >> 2, y);
    }
}

// ---------------------------------------------------------------------------
extern "C" void kernel_launch(void* const* d_in, const int* in_sizes, int n_in,
                              void* d_out, int out_size)
{
    (void)in_sizes; (void)n_in; (void)out_size;
    const float* xq  = (const float*)d_in[0];
    const float* tmk = (const float*)d_in[1];
    const float* tmv = (const float*)d_in[2];
    const float* tmr = (const float*)d_in[3];
    const float* tmg = (const float*)d_in[4];
    const float* td  = (const float*)d_in[5];
    const float* tf  = (const float*)d_in[6];
    const float* Wr  = (const float*)d_in[7];
    const float* Wk  = (const float*)d_in[8];
    const float* Wv  = (const float*)d_in[9];
    const float* Wg  = (const float*)d_in[10];
    const float* Wo  = (const float*)d_in[11];
    const float* lnw = (const float*)d_in[12];
    const float* lnb = (const float*)d_in[13];
    float* out = (float*)d_out;

    __half* h16; cudaGetSymbolAddress((void**)&h16, g_h16);
    float*  f32; cudaGetSymbolAddress((void**)&f32, g_f32);
    __half* w16; cudaGetSymbolAddress((void**)&w16, g_w16);

    const size_t HS = (size_t)MTOK * Cn;
    const size_t WS = (size_t)Cn * Cn;
    __half* H[10]; for (int i = 0; i < 10; i++) H[i] = h16 + (size_t)i * HS;
    float*  F[4];  for (int i = 0; i < 4; i++)  F[i] = f32 + (size_t)i * HS;
    __half* W16[10]; for (int i = 0; i < 10; i++) W16[i] = w16 + (size_t)i * WS;

    // 1) mix + split to fp16 hi/lo
    mix_split<<<(MTOK * Cn / 4) / 256, 256>>>(xq, tmr, tmk, tmv, tmg);

    // 1b) weight splits
    const float* Ws[5] = {Wr, Wk, Wv, Wg, Wo};
    for (int i = 0; i < 5; i++)
        wsplit<<<(Cn * Cn / 4) / 256, 256>>>(Ws[i], W16[2 * i], W16[2 * i + 1]);

    // 2) HMMA projections
    cudaFuncSetAttribute(gemm16, cudaFuncAttributeMaxDynamicSharedMemorySize, GEMM_SMEM);
    dim3 gg(Cn / BN, MTOK / BM);   // (8, 128)
    gemm16<<<gg, 256, GEMM_SMEM>>>(H[0], H[1], W16[0], W16[1], F[0], 0);  // r
    gemm16<<<gg, 256, GEMM_SMEM>>>(H[2], H[3], W16[2], W16[3], F[1], 0);  // k
    gemm16<<<gg, 256, GEMM_SMEM>>>(H[4], H[5], W16[4], W16[5], F[2], 0);  // v
    gemm16<<<gg, 256, GEMM_SMEM>>>(H[6], H[7], W16[6], W16[7], F[3], 1);  // g (SiLU)

    // 3) attention
    int smA = 2 * 128 * 68 * 4;
    cudaFuncSetAttribute(states_kernel, cudaFuncAttributeMaxDynamicSharedMemorySize, smA);
    states_kernel<<<Bn * Hn, 256, smA>>>(td);

    cudaFuncSetAttribute(passB_kernel, cudaFuncAttributeMaxDynamicSharedMemorySize, PB_SMEM);
    passB_kernel<<<Nch * Bn * Hn, 256, PB_SMEM>>>(td, tf, lnw, lnb);

    // 4) output projection
    gemm16<<<gg, 256, GEMM_SMEM>>>(H[8], H[9], W16[8], W16[9], out, 0);
}

// round 9
// speedup vs baseline: 2.3465x; 1.2284x over previous
#include <cuda_runtime.h>
#include <cuda_fp16.h>
#include <cstdint>

// Problem constants
#define Bn   4
#define TTn  4096
#define Cn   1024
#define Hn   16
#define Kn   64
#define Tn   128
#define Nch  32
#define MTOK (Bn*TTn)          // 16384 tokens

// Scratch:
//  g_h16: fp16 hi/lo pairs: 0/1=xr 2/3=xk 4/5=xv 6/7=xg 8/9=yg   (10 x 32MB)
//  g_f32: 0=r 1=k 2=v 3=g (fp32 for attention)                    (4 x 64MB)
//  g_w16: weight hi/lo: 0/1=Wr 2/3=Wk 4/5=Wv 6/7=Wg 8/9=Wo        (10 x 2MB)
__device__ __half g_h16[10][(size_t)MTOK * Cn];
__device__ float  g_f32[4][(size_t)MTOK * Cn];
__device__ __half g_w16[10][(size_t)Cn * Cn];
__device__ float  g_states[(size_t)Nch * Bn * Hn * Kn * Kn];

// ---------------------------------------------------------------------------
// helpers (baseline PTX only: cp.async sm_80, ldmatrix sm_75, mma.sync sm_80)
// ---------------------------------------------------------------------------
__device__ __forceinline__ uint32_t s2u(const void* p) {
    return (uint32_t)__cvta_generic_to_shared(p);
}
#define CP16(dst, src) asm volatile("cp.async.cg.shared.global [%0], [%1], 16;" :: "r"(dst), "l"(src) : "memory")
#define CP_COMMIT()    asm volatile("cp.async.commit_group;" ::: "memory")
#define CP_WAIT1()     asm volatile("cp.async.wait_group 1;" ::: "memory")
#define CP_WAIT0()     asm volatile("cp.async.wait_group 0;" ::: "memory")

#define LDSM4(r, a) asm volatile( \
    "ldmatrix.sync.aligned.m8n8.x4.shared.b16 {%0,%1,%2,%3}, [%4];" \
    : "=r"((r)[0]), "=r"((r)[1]), "=r"((r)[2]), "=r"((r)[3]) : "r"(a))

#define MMA16816(c, a, b) asm volatile( \
    "mma.sync.aligned.m16n8k16.row.col.f32.f16.f16.f32 " \
    "{%0,%1,%2,%3}, {%4,%5,%6,%7}, {%8,%9}, {%0,%1,%2,%3};" \
    : "+f"((c)[0]), "+f"((c)[1]), "+f"((c)[2]), "+f"((c)[3]) \
    : "r"((a)[0]), "r"((a)[1]), "r"((a)[2]), "r"((a)[3]), \
      "r"((b)[0]), "r"((b)[1]))

__device__ __forceinline__ uint32_t swz(uint32_t o) { return o ^ ((o >> 3) & 0x70); }

// fp32 -> fp16 hi/lo split, 4 elements, packed stores
__device__ __forceinline__ void split_store4(__half* hb, __half* lb, size_t idx4, float4 o) {
    __half h0 = __float2half_rn(o.x), h1 = __float2half_rn(o.y);
    __half h2 = __float2half_rn(o.z), h3 = __float2half_rn(o.w);
    __half l0 = __float2half_rn(o.x - __half2float(h0));
    __half l1 = __float2half_rn(o.y - __half2float(h1));
    __half l2 = __float2half_rn(o.z - __half2float(h2));
    __half l3 = __float2half_rn(o.w - __half2float(h3));
    uint2 hv, lv;
    hv.x = (uint32_t)__half_as_ushort(h0) | ((uint32_t)__half_as_ushort(h1) << 16);
    hv.y = (uint32_t)__half_as_ushort(h2) | ((uint32_t)__half_as_ushort(h3) << 16);
    lv.x = (uint32_t)__half_as_ushort(l0) | ((uint32_t)__half_as_ushort(l1) << 16);
    lv.y = (uint32_t)__half_as_ushort(l2) | ((uint32_t)__half_as_ushort(l3) << 16);
    ((uint2*)hb)[idx4] = hv;
    ((uint2*)lb)[idx4] = lv;
}

// ---------------------------------------------------------------------------
// 1) time-shift + 4-way mix -> fp16 hi/lo outputs
// ---------------------------------------------------------------------------
__global__ void __launch_bounds__(256) mix_split(
    const float* __restrict__ x,
    const float* __restrict__ mr, const float* __restrict__ mk,
    const float* __restrict__ mv, const float* __restrict__ mg)
{
    int idx = blockIdx.x * 256 + threadIdx.x;   // over MTOK*Cn/4
    const int C4 = Cn / 4;
    int c4  = idx & (C4 - 1);
    int tok = idx >> 8;
    int t   = tok & (TTn - 1);

    float4 xc = ((const float4*)x)[idx];
    float4 xp = make_float4(0.f, 0.f, 0.f, 0.f);
    if (t > 0) xp = ((const float4*)x)[idx - C4];

    const float* mixes[4] = {mr, mk, mv, mg};
#pragma unroll
    for (int m = 0; m < 4; m++) {
        float4 f = ((const float4*)mixes[m])[c4];
        float4 o;
        o.x = xc.x * f.x + xp.x * (1.f - f.x);
        o.y = xc.y * f.y + xp.y * (1.f - f.y);
        o.z = xc.z * f.z + xp.z * (1.f - f.z);
        o.w = xc.w * f.w + xp.w * (1.f - f.w);
        split_store4(g_h16[2 * m], g_h16[2 * m + 1], (size_t)idx, o);
    }
}

// ---------------------------------------------------------------------------
// 1b) weight fp32 -> fp16 hi/lo, all 5 weights in one launch (grid.y = 5)
// ---------------------------------------------------------------------------
__global__ void __launch_bounds__(256) wsplit5(
    const float* __restrict__ W0, const float* __restrict__ W1,
    const float* __restrict__ W2, const float* __restrict__ W3,
    const float* __restrict__ W4)
{
    int m = blockIdx.y;
    const float* W = (m == 0) ? W0 : (m == 1) ? W1 : (m == 2) ? W2 : (m == 3) ? W3 : W4;
    int idx = blockIdx.x * 256 + threadIdx.x;   // over Cn*Cn/4
    float4 w = ((const float4*)W)[idx];
    split_store4(g_w16[2 * m], g_w16[2 * m + 1], (size_t)idx, w);
}

// ---------------------------------------------------------------------------
// 2) HMMA fp16-split GEMM:  Y[M,N] = A[M,K] * W[N,K]^T  (fp32-accurate)
//    BM=BN=128, BK=32, 3-stage cp.async pipeline, mma.sync.m16n8k16
//    8 warps: warp_m = wid&1 (64 rows), warp_n = wid>>1 (32 cols)
//    2 CTAs/SM (192KB smem, <=128 regs)
// ---------------------------------------------------------------------------
#define BM 128
#define BN 128
#define BK 32
#define NCHUNK (Cn / BK)        // 32
#define TILE_B (BM * BK * 2)    // 8192 bytes per half-tile
#define STG_BYTES (4 * TILE_B)  // 32768 (Ahi, Alo, Bhi, Blo)
#define GEMM_SMEM (3 * STG_BYTES)

__device__ __forceinline__ void gemm_body(
    const __half* __restrict__ Ahi, const __half* __restrict__ Alo,
    const __half* __restrict__ Bhi, const __half* __restrict__ Blo,
    float* __restrict__ Y, int act, char* smem)
{
    uint32_t sb = s2u(smem);
    int tid = threadIdx.x, wid = tid >> 5, lane = tid & 31;
    int bm = blockIdx.y << 7;
    int bn = blockIdx.x << 7;
    int wm = (wid & 1) << 6;    // 0 / 64
    int wn = (wid >> 1) << 5;   // 0 / 32 / 64 / 96

    auto load_stage = [&](int s, int c) {
        uint32_t so = sb + (uint32_t)s * STG_BYTES;
#pragma unroll
        for (int i = 0; i < 2; i++) {
            int idx = tid + (i << 8);          // 0..511
            int row = idx >> 2;                // 0..127
            uint32_t cb = (idx & 3) << 4;      // 0,16,32,48 bytes
            uint32_t d = swz(row * 64 + cb);
            size_t go = ((size_t)(bm + row) << 11) + (size_t)c * 64 + cb;
            CP16(so + d,         (const char*)Ahi + go);
            CP16(so + 8192 + d,  (const char*)Alo + go);
            size_t gb = ((size_t)(bn + row) << 11) + (size_t)c * 64 + cb;
            CP16(so + 16384 + d, (const char*)Bhi + gb);
            CP16(so + 24576 + d, (const char*)Blo + gb);
        }
        CP_COMMIT();
    };

    float acc[4][4][4];
#pragma unroll
    for (int mt = 0; mt < 4; mt++)
#pragma unroll
        for (int nt = 0; nt < 4; nt++)
#pragma unroll
            for (int q = 0; q < 4; q++) acc[mt][nt][q] = 0.f;

    load_stage(0, 0);
    load_stage(1, 1);

    for (int c = 0; c < NCHUNK; c++) {
        int s = c % 3;
        if (c + 2 < NCHUNK) CP_WAIT1(); else CP_WAIT0();
        __syncthreads();
        if (c + 2 < NCHUNK) load_stage((c + 2) % 3, c + 2);

        uint32_t so = sb + (uint32_t)s * STG_BYTES;
#pragma unroll
        for (int s16 = 0; s16 < 2; s16++) {
            uint32_t ah[4][4], bh[4][2];
#pragma unroll
            for (int mt = 0; mt < 4; mt++) {
                int row = wm + mt * 16 + (lane & 15);
                uint32_t o = swz(row * 64 + s16 * 32 + ((lane >> 4) << 4));
                LDSM4(ah[mt], so + o);
            }
#pragma unroll
            for (int bt = 0; bt < 2; bt++) {
                int row = wn + bt * 16 + (lane & 15);
                uint32_t o = swz(row * 64 + s16 * 32 + ((lane >> 4) << 4));
                uint32_t r[4];
                LDSM4(r, so + 16384 + o);
                bh[2 * bt][0] = r[0]; bh[2 * bt][1] = r[2];
                bh[2 * bt + 1][0] = r[1]; bh[2 * bt + 1][1] = r[3];
            }
            // phase 1: hi*hi and lo*hi (al lives only here)
            {
                uint32_t al[4][4];
#pragma unroll
                for (int mt = 0; mt < 4; mt++) {
                    int row = wm + mt * 16 + (lane & 15);
                    uint32_t o = swz(row * 64 + s16 * 32 + ((lane >> 4) << 4));
                    LDSM4(al[mt], so + 8192 + o);
                }
#pragma unroll
                for (int mt = 0; mt < 4; mt++)
#pragma unroll
                    for (int nt = 0; nt < 4; nt++) {
                        MMA16816(acc[mt][nt], ah[mt], bh[nt]);
                        MMA16816(acc[mt][nt], al[mt], bh[nt]);
                    }
            }
            // phase 2: hi*lo (bl lives only here)
            {
                uint32_t bl[4][2];
#pragma unroll
                for (int bt = 0; bt < 2; bt++) {
                    int row = wn + bt * 16 + (lane & 15);
                    uint32_t o = swz(row * 64 + s16 * 32 + ((lane >> 4) << 4));
                    uint32_t r[4];
                    LDSM4(r, so + 24576 + o);
                    bl[2 * bt][0] = r[0]; bl[2 * bt][1] = r[2];
                    bl[2 * bt + 1][0] = r[1]; bl[2 * bt + 1][1] = r[3];
                }
#pragma unroll
                for (int mt = 0; mt < 4; mt++)
#pragma unroll
                    for (int nt = 0; nt < 4; nt++)
                        MMA16816(acc[mt][nt], ah[mt], bl[nt]);
            }
        }
    }

    // epilogue
#pragma unroll
    for (int mt = 0; mt < 4; mt++) {
        int r0 = bm + wm + mt * 16 + (lane >> 2);
#pragma unroll
        for (int nt = 0; nt < 4; nt++) {
            int col = bn + wn + nt * 8 + ((lane & 3) << 1);
            float v0 = acc[mt][nt][0], v1 = acc[mt][nt][1];
            float v2 = acc[mt][nt][2], v3 = acc[mt][nt][3];
            if (act) {
                v0 = v0 / (1.f + expf(-v0));
                v1 = v1 / (1.f + expf(-v1));
                v2 = v2 / (1.f + expf(-v2));
                v3 = v3 / (1.f + expf(-v3));
            }
            *(float2*)(Y + (size_t)r0 * Cn + col)       = make_float2(v0, v1);
            *(float2*)(Y + (size_t)(r0 + 8) * Cn + col) = make_float2(v2, v3);
        }
    }
}

__global__ void __launch_bounds__(256, 2)
gemm16(const __half* __restrict__ Ahi, const __half* __restrict__ Alo,
       const __half* __restrict__ Bhi, const __half* __restrict__ Blo,
       float* __restrict__ Y, int act)
{
    extern __shared__ char smem[];
    gemm_body(Ahi, Alo, Bhi, Blo, Y, act, smem);
}

// batched: all 4 projections in one launch (grid.z = 0..3: r,k,v,g)
__global__ void __launch_bounds__(256, 2) gemm16x4()
{
    extern __shared__ char smem[];
    int m = blockIdx.z;
    gemm_body(g_h16[2 * m], g_h16[2 * m + 1], g_w16[2 * m], g_w16[2 * m + 1],
              g_f32[m], m == 3 ? 1 : 0, smem);
}

// ---------------------------------------------------------------------------
// 3a) Per-chunk state contributions U_n = (k .* wk)^T @ v — fully parallel
// ---------------------------------------------------------------------------
__global__ void __launch_bounds__(256) states_U(const float* __restrict__ td)
{
    extern __shared__ float sm[];
    float* ks = sm;                 // [128][68] : k[j][kk] * wk[j]
    float* vs = sm + 128 * 68;      // [128][68]

    int bidx = blockIdx.x;
    int n = bidx >> 6, bh = bidx & 63, b = bh >> 4, h = bh & 15;
    float et = expf(td[h]);

    int tid = threadIdx.x;
    int tr = tid >> 4, tc = tid & 15;

    const float* kc_ = &g_f32[1][((size_t)(b * TTn + n * Tn)) * Cn + h * Kn];
    const float* vc_ = &g_f32[2][((size_t)(b * TTn + n * Tn)) * Cn + h * Kn];
#pragma unroll
    for (int l = 0; l < 8; l++) {
        int t4  = tid + (l << 8);
        int row = t4 >> 4;
        int kc  = (t4 & 15) << 2;
        float4 kv = *(const float4*)(kc_ + (size_t)row * Cn + kc);
        float wkj = expf(-et * (float)(127 - row));
        ks[row * 68 + kc + 0] = kv.x * wkj;
        ks[row * 68 + kc + 1] = kv.y * wkj;
        ks[row * 68 + kc + 2] = kv.z * wkj;
        ks[row * 68 + kc + 3] = kv.w * wkj;
        float4 vv = *(const float4*)(vc_ + (size_t)row * Cn + kc);
        *(float4*)&vs[row * 68 + kc] = vv;
    }
    __syncthreads();

    float S[4][4];
#pragma unroll
    for (int i = 0; i < 4; i++)
#pragma unroll
        for (int j = 0; j < 4; j++) S[i][j] = 0.f;

    for (int j = 0; j < 128; j++) {
        float4 a  = *(float4*)&ks[j * 68 + (tr << 2)];
        float4 v4 = *(float4*)&vs[j * 68 + (tc << 2)];
        S[0][0] = fmaf(a.x, v4.x, S[0][0]); S[0][1] = fmaf(a.x, v4.y, S[0][1]);
        S[0][2] = fmaf(a.x, v4.z, S[0][2]); S[0][3] = fmaf(a.x, v4.w, S[0][3]);
        S[1][0] = fmaf(a.y, v4.x, S[1][0]); S[1][1] = fmaf(a.y, v4.y, S[1][1]);
        S[1][2] = fmaf(a.y, v4.z, S[1][2]); S[1][3] = fmaf(a.y, v4.w, S[1][3]);
        S[2][0] = fmaf(a.z, v4.x, S[2][0]); S[2][1] = fmaf(a.z, v4.y, S[2][1]);
        S[2][2] = fmaf(a.z, v4.z, S[2][2]); S[2][3] = fmaf(a.z, v4.w, S[2][3]);
        S[3][0] = fmaf(a.w, v4.x, S[3][0]); S[3][1] = fmaf(a.w, v4.y, S[3][1]);
        S[3][2] = fmaf(a.w, v4.z, S[3][2]); S[3][3] = fmaf(a.w, v4.w, S[3][3]);
    }

    float* st = &g_states[(((size_t)n * Bn + b) * Hn + h) * (Kn * Kn)];
#pragma unroll
    for (int i = 0; i < 4; i++)
#pragma unroll
        for (int j = 0; j < 4; j++)
            st[(tr * 4 + i) * 64 + tc * 4 + j] = S[i][j];
}

// ---------------------------------------------------------------------------
// 3b) Scalar-coefficient prefix scan: g_states[n] := entry state S_n.
//     One thread per (b,h,element): 262144 threads, coalesced.
// ---------------------------------------------------------------------------
__global__ void __launch_bounds__(256) states_scan(const float* __restrict__ td)
{
    int idx = blockIdx.x * 256 + threadIdx.x;    // 0 .. 262143
    int e  = idx & 4095;
    int bh = idx >> 12;
    int h  = bh & 15;
    float ws = expf(-expf(td[h]) * 128.f);

    float s = 0.f;
#pragma unroll
    for (int n = 0; n < Nch; n++) {
        size_t off = ((size_t)n * 64 + bh) * 4096 + e;
        float u = g_states[off];
        g_states[off] = s;
        s = ws * s + u;
    }
}

// ---------------------------------------------------------------------------
// 4) Pass B: intra-chunk attention + state + GroupNorm + *g -> yg (fp16 hi/lo)
// ---------------------------------------------------------------------------
#define PB_SMEM ((64*132*2 + 128*68 + 64*68 + 128*132 + 3*128) * 4)

__global__ void __launch_bounds__(256, 1) passB_kernel(
    const float* __restrict__ td, const float* __restrict__ tf,
    const float* __restrict__ lnw, const float* __restrict__ lnb)
{
    extern __shared__ float sm[];
    float* rT   = sm;                    // [64][132]
    float* kT   = rT + 64 * 132;         // [64][132]
    float* vsm  = kT + 64 * 132;         // [128][68]
    float* Ssm  = vsm + 128 * 68;        // [64][68]
    float* att  = Ssm + 64 * 68;         // [128][132]; reused as out[128][68]
    float* dp   = att + 128 * 132;       // [128]
    float* mu_s = dp + 128;
    float* rs_s = mu_s + 128;

    int bidx = blockIdx.x;
    int n = bidx >> 6, bh = bidx & 63, b = bh >> 4, h = bh & 15;
    int tid = threadIdx.x;
    int tr = tid >> 4, tc = tid & 15;

    float et = expf(td[h]);
    float u  = tf[h];
    if (tid < 128) dp[tid] = expf(-et * (float)tid);

    const size_t base = ((size_t)(b * TTn + n * Tn)) * Cn + h * Kn;
    const float* rg = &g_f32[0][base];
    const float* kg = &g_f32[1][base];
    const float* vg = &g_f32[2][base];

#pragma unroll
    for (int l = 0; l < 8; l++) {
        int t4  = tid + (l << 8);
        int row = t4 >> 4;
        int kc  = (t4 & 15) << 2;
        float4 rv = *(const float4*)(rg + (size_t)row * Cn + kc);
        rT[(kc + 0) * 132 + row] = rv.x; rT[(kc + 1) * 132 + row] = rv.y;
        rT[(kc + 2) * 132 + row] = rv.z; rT[(kc + 3) * 132 + row] = rv.w;
        float4 kv = *(const float4*)(kg + (size_t)row * Cn + kc);
        kT[(kc + 0) * 132 + row] = kv.x; kT[(kc + 1) * 132 + row] = kv.y;
        kT[(kc + 2) * 132 + row] = kv.z; kT[(kc + 3) * 132 + row] = kv.w;
        float4 vv = *(const float4*)(vg + (size_t)row * Cn + kc);
        *(float4*)&vsm[row * 68 + kc] = vv;
    }
    const float* Sg = &g_states[(((size_t)n * Bn + b) * Hn + h) * (Kn * Kn)];
#pragma unroll
    for (int l = 0; l < 4; l++) {
        int t4  = tid + (l << 8);
        int row = t4 >> 4;
        int kc  = (t4 & 15) << 2;
        *(float4*)&Ssm[row * 68 + kc] = *(const float4*)(Sg + row * 64 + kc);
    }
    __syncthreads();

    // ---- stage 1: att = (r @ k^T) .* w_mat ----
    {
        float acc[8][8];
#pragma unroll
        for (int i = 0; i < 8; i++)
#pragma unroll
            for (int j = 0; j < 8; j++) acc[i][j] = 0.f;

        for (int kk = 0; kk < 64; kk++) {
            float4 a0 = *(float4*)&rT[kk * 132 + (tr << 3) + 0];
            float4 a1 = *(float4*)&rT[kk * 132 + (tr << 3) + 4];
            float4 b0 = *(float4*)&kT[kk * 132 + (tc << 3) + 0];
            float4 b1 = *(float4*)&kT[kk * 132 + (tc << 3) + 4];
            float ar[8] = {a0.x, a0.y, a0.z, a0.w, a1.x, a1.y, a1.z, a1.w};
            float br[8] = {b0.x, b0.y, b0.z, b0.w, b1.x, b1.y, b1.z, b1.w};
#pragma unroll
            for (int i = 0; i < 8; i++)
#pragma unroll
                for (int j = 0; j < 8; j++)
                    acc[i][j] = fmaf(ar[i], br[j], acc[i][j]);
        }
#pragma unroll
        for (int i = 0; i < 8; i++) {
            int row = (tr << 3) + i;
#pragma unroll
            for (int j = 0; j < 8; j++) {
                int col = (tc << 3) + j;
                float w = (row > col) ? dp[row - col - 1] : ((row == col) ? u : 0.f);
                att[row * 132 + col] = acc[i][j] * w;
            }
        }
    }
    __syncthreads();

    // ---- stage 2: out = att@v + diag(wb) * (r@S) ----
    float a2[8][4], aS[8][4];
#pragma unroll
    for (int i = 0; i < 8; i++)
#pragma unroll
        for (int j = 0; j < 4; j++) { a2[i][j] = 0.f; aS[i][j] = 0.f; }

    for (int j = 0; j < 128; j++) {
        float4 bv = *(float4*)&vsm[j * 68 + (tc << 2)];
#pragma unroll
        for (int i = 0; i < 8; i++) {
            float a = att[((tr << 3) + i) * 132 + j];
            a2[i][0] = fmaf(a, bv.x, a2[i][0]);
            a2[i][1] = fmaf(a, bv.y, a2[i][1]);
            a2[i][2] = fmaf(a, bv.z, a2[i][2]);
            a2[i][3] = fmaf(a, bv.w, a2[i][3]);
        }
    }
    for (int kk = 0; kk < 64; kk++) {
        float4 a0 = *(float4*)&rT[kk * 132 + (tr << 3) + 0];
        float4 a1 = *(float4*)&rT[kk * 132 + (tr << 3) + 4];
        float4 bs = *(float4*)&Ssm[kk * 68 + (tc << 2)];
        float ar[8] = {a0.x, a0.y, a0.z, a0.w, a1.x, a1.y, a1.z, a1.w};
#pragma unroll
        for (int i = 0; i < 8; i++) {
            aS[i][0] = fmaf(ar[i], bs.x, aS[i][0]);
            aS[i][1] = fmaf(ar[i], bs.y, aS[i][1]);
            aS[i][2] = fmaf(ar[i], bs.z, aS[i][2]);
            aS[i][3] = fmaf(ar[i], bs.w, aS[i][3]);
        }
    }
    __syncthreads();

#pragma unroll
    for (int i = 0; i < 8; i++) {
        int row = (tr << 3) + i;
        float wb = dp[row];
        float4 o;
        o.x = a2[i][0] + wb * aS[i][0];
        o.y = a2[i][1] + wb * aS[i][1];
        o.z = a2[i][2] + wb * aS[i][2];
        o.w = a2[i][3] + wb * aS[i][3];
        *(float4*)&att[row * 68 + (tc << 2)] = o;
    }
    __syncthreads();

    if (tid < 128) {
        float s1 = 0.f, s2 = 0.f;
        const float* orow = &att[tid * 68];
#pragma unroll
        for (int c = 0; c < 64; c++) {
            float v = orow[c] * 0.125f;
            s1 += v; s2 += v * v;
        }
        float mu  = s1 * (1.f / 64.f);
        float var = s2 * (1.f / 64.f) - mu * mu;
        mu_s[tid] = mu;
        rs_s[tid] = rsqrtf(var + 1e-5f);
    }
    __syncthreads();

    const float* gg = &g_f32[3][base];
#pragma unroll
    for (int l = 0; l < 8; l++) {
        int t4  = tid + (l << 8);
        int row = t4 >> 4;
        int kc  = (t4 & 15) << 2;
        float mu = mu_s[row], rs = rs_s[row];
        float4 o  = *(float4*)&att[row * 68 + kc];
        float4 w4 = *(const float4*)(lnw + h * 64 + kc);
        float4 b4 = *(const float4*)(lnb + h * 64 + kc);
        float4 g4 = *(const float4*)(gg + (size_t)row * Cn + kc);
        float4 y;
        y.x = ((o.x * 0.125f - mu) * rs * w4.x + b4.x) * g4.x;
        y.y = ((o.y * 0.125f - mu) * rs * w4.y + b4.y) * g4.y;
        y.z = ((o.z * 0.125f - mu) * rs * w4.z + b4.z) * g4.z;
        y.w = ((o.w * 0.125f - mu) * rs * w4.w + b4.w) * g4.w;
        size_t e = base + (size_t)row * Cn + kc;
        split_store4(g_h16[8], g_h16[9], e >> 2, y);
    }
}

// ---------------------------------------------------------------------------
extern "C" void kernel_launch(void* const* d_in, const int* in_sizes, int n_in,
                              void* d_out, int out_size)
{
    (void)in_sizes; (void)n_in; (void)out_size;
    const float* xq  = (const float*)d_in[0];
    const float* tmk = (const float*)d_in[1];
    const float* tmv = (const float*)d_in[2];
    const float* tmr = (const float*)d_in[3];
    const float* tmg = (const float*)d_in[4];
    const float* td  = (const float*)d_in[5];
    const float* tf  = (const float*)d_in[6];
    const float* Wr  = (const float*)d_in[7];
    const float* Wk  = (const float*)d_in[8];
    const float* Wv  = (const float*)d_in[9];
    const float* Wg  = (const float*)d_in[10];
    const float* Wo  = (const float*)d_in[11];
    const float* lnw = (const float*)d_in[12];
    const float* lnb = (const float*)d_in[13];
    float* out = (float*)d_out;

    __half* h16; cudaGetSymbolAddress((void**)&h16, g_h16);
    __half* w16; cudaGetSymbolAddress((void**)&w16, g_w16);
    const size_t HS = (size_t)MTOK * Cn;
    const size_t WS = (size_t)Cn * Cn;

    // 1) mix + split to fp16 hi/lo
    mix_split<<<(MTOK * Cn / 4) / 256, 256>>>(xq, tmr, tmk, tmv, tmg);

    // 1b) weight splits (one launch)
    wsplit5<<<dim3((Cn * Cn / 4) / 256, 5), 256>>>(Wr, Wk, Wv, Wg, Wo);

    // 2) HMMA projections, batched (r,k,v,g)
    cudaFuncSetAttribute(gemm16x4, cudaFuncAttributeMaxDynamicSharedMemorySize, GEMM_SMEM);
    cudaFuncSetAttribute(gemm16,   cudaFuncAttributeMaxDynamicSharedMemorySize, GEMM_SMEM);
    gemm16x4<<<dim3(Cn / BN, MTOK / BM, 4), 256, GEMM_SMEM>>>();

    // 3) attention states: parallel U + scalar scan
    int smU = 2 * 128 * 68 * 4;
    cudaFuncSetAttribute(states_U, cudaFuncAttributeMaxDynamicSharedMemorySize, smU);
    states_U<<<Nch * Bn * Hn, 256, smU>>>(td);
    states_scan<<<(Bn * Hn * Kn * Kn) / 256, 256>>>(td);

    // 4) pass B
    cudaFuncSetAttribute(passB_kernel, cudaFuncAttributeMaxDynamicSharedMemorySize, PB_SMEM);
    passB_kernel<<<Nch * Bn * Hn, 256, PB_SMEM>>>(td, tf, lnw, lnb);

    // 5) output projection
    gemm16<<<dim3(Cn / BN, MTOK / BM), 256, GEMM_SMEM>>>(
        h16 + 8 * HS, h16 + 9 * HS, w16 + 8 * WS, w16 + 9 * WS, out, 0);
}